// round 12
// baseline (speedup 1.0000x reference)
#include <cuda_runtime.h>
#include <cuda_bf16.h>

// Problem constants (single species, e3tb 1s+1p+1d, K=4, A=192, E=3072)
#define AA 192
#define EE 3072
#define KK 4
#define PP 58
#define SS 18                          // spin_deg * norb
#define SQ (SS*SS)                     // 324
#define NN (AA*SS)                     // 3456
#define NPAIR (AA*AA)                  // 36864
#define OUTC ((long long)KK*NN*NN)     // complex64 elements = 47,775,744

// Scratch (__device__ globals)
__device__ float g_hopRot[EE * SQ];
__device__ float g_onRot [AA * SQ];
__device__ int   g_eidx  [2 * EE];
__device__ int   g_cnt   [NPAIR];
__device__ int   g_off   [NPAIR];
__device__ int   g_cur   [NPAIR];
__device__ int   g_list  [EE];
__device__ float g_phc   [EE * KK];
__device__ float g_phs   [EE * KK];
__device__ int   g_bf    [5];          // per-float-buffer bf16 flag
__device__ int   g_is64;               // edge_index dtype flag

// ---------------------------------------------------------------------------
// Dtype-agnostic float load: idx is an ELEMENT index; byte extent touched is
// 2*idx (bf16) or 4*idx (f32), matching the detected dtype's true allocation.
__device__ __forceinline__ float loadF(const void* p, long long i, int bf) {
    if (bf) return __bfloat162float(((const __nv_bfloat16*)p)[i]);
    return ((const float*)p)[i];
}

__global__ void k_zero(float* p, long long nFloats) {
    long long i = (long long)blockIdx.x * blockDim.x + threadIdx.x;
    long long st = (long long)gridDim.x * blockDim.x;
    while (i < nFloats) { p[i] = 0.0f; i += st; }
}

// Detect dtypes and normalize edge_index. ALL reads stay within words < n/2
// for float buffers (present under bf16 OR f32) and words < 2*EE for eidx
// (present under int32 OR int64); int64 far reads only on data evidence.
__global__ void k_detect(const void* hop, const void* ons, const void* Rm,
                         const void* kp, const void* sh,
                         const unsigned int* eidx) {
    __shared__ int cnt[5];
    __shared__ int nz;
    const int t = threadIdx.x;   // 512
    if (t < 5) cnt[t] = 0;
    if (t == 0) nz = 0;
    __syncthreads();

    const void* bufs[5] = { hop, ons, Rm, kp, sh };
    const long long nels[5] = { (long long)EE * PP, (long long)AA * PP,
                                (long long)AA * SQ, KK * 3, EE * 3 };
    if (t < 256) {
        for (int b = 0; b < 5; ++b) {
            long long maxW = nels[b] / 2;            // words provably present
            long long w = ((long long)t * maxW) / 256;
            if (w >= maxW) w = maxW - 1;
            if (w < 0) w = 0;
            unsigned int word = ((const unsigned int*)bufs[b])[w];
            int m = (int)((word >> 8) & 0x7F);       // bf16: sign-stripped exp bits
            if (m >= 0x35 && m <= 0x44) atomicAdd(&cnt[b], 1);
        }
    }
    int local = 0;
    for (int w = 1 + 2 * t; w < 2 * EE; w += 2 * 512)
        if (eidx[w] != 0u) local = 1;                // int64 in [0,192): odd words 0
    if (local) atomicOr(&nz, 1);
    __syncthreads();

    if (t < 5) g_bf[t] = (cnt[t] >= 64) ? 1 : 0;     // ambiguous => bf16 (safe)
    const int is64 = (nz == 0);
    if (t == 0) g_is64 = is64;
    for (int n = t; n < 2 * EE; n += 512) {
        int v = is64 ? (int)eidx[2 * n] : (int)eidx[n];
        if (v < 0) v = 0;
        if (v >= AA) v = AA - 1;
        g_eidx[n] = v;
    }
}

__global__ void k_clr() {
    int i = blockIdx.x * blockDim.x + threadIdx.x;
    if (i < NPAIR) { g_cnt[i] = 0; g_cur[i] = 0; }
}
__global__ void k_count() {
    int e = blockIdx.x * blockDim.x + threadIdx.x;
    if (e < EE) atomicAdd(&g_cnt[g_eidx[e] * AA + g_eidx[EE + e]], 1);
}
__global__ void k_scan() {   // single-CTA exclusive prefix sum over NPAIR
    __shared__ int partial[512];
    const int T = 512, CHUNK = NPAIR / T;   // 72
    int tid = threadIdx.x;
    int s = 0;
    for (int i = tid * CHUNK; i < (tid + 1) * CHUNK; ++i) s += g_cnt[i];
    partial[tid] = s;
    __syncthreads();
    if (tid == 0) {
        int acc = 0;
        for (int i = 0; i < T; ++i) { int v = partial[i]; partial[i] = acc; acc += v; }
    }
    __syncthreads();
    int acc = partial[tid];
    for (int i = tid * CHUNK; i < (tid + 1) * CHUNK; ++i) { g_off[i] = acc; acc += g_cnt[i]; }
}
__global__ void k_fill() {
    int e = blockIdx.x * blockDim.x + threadIdx.x;
    if (e < EE) {
        int pair = g_eidx[e] * AA + g_eidx[EE + e];
        int pos = g_off[pair] + atomicAdd(&g_cur[pair], 1);
        if (pos >= 0 && pos < EE) g_list[pos] = e;
    }
}

__global__ void k_phase(const void* kpts, const void* shift) {
    int idx = blockIdx.x * blockDim.x + threadIdx.x;
    if (idx < EE * KK) {
        const int bfK = g_bf[3], bfS = g_bf[4];
        int e = idx / KK, k = idx % KK;
        float d = 0.f;
        for (int c = 0; c < 3; ++c)
            d += loadF(kpts, k * 3 + c, bfK) * loadF(shift, e * 3 + c, bfS);
        float sn, cs;
        sincosf(-6.283185307179586f * d, &sn, &cs);   // exp(-2*pi*i*d)
        g_phc[idx] = cs;
        g_phs[idx] = sn;
    }
}

__device__ void featmap(int po, int qo, int* p, float* f) {
    int bi = (po == 0) ? 0 : (po < 4 ? 1 : 2);
    int bj = (qo == 0) ? 0 : (qo < 4 ? 1 : 2);
    if (bi > bj) { *p = -1; *f = 0.f; return; }
    *f = (bi == bj) ? 0.5f : 1.0f;
    int ri = po - (bi == 0 ? 0 : (bi == 1 ? 1 : 4));
    int ci = qo - (bj == 0 ? 0 : (bj == 1 ? 1 : 4));
    int jo = (bj == 0 ? 1 : (bj == 1 ? 3 : 5));
    int b;
    if (bi == 0)      b = (bj == 0) ? 0 : (bj == 1 ? 1 : 4);
    else if (bi == 1) b = (bj == 1) ? 9 : 18;
    else              b = 33;
    *p = b + ri * jo + ci;
}

// out = Rs @ H2 @ Rd^T, spin-interleaved doubling H2[2po+s,2qo+s]=Horb[po,qo].
__global__ void k_rotate(const void* feats, const void* R, int isOnsite) {
    const int e = blockIdx.x;
    __shared__ float Rs[SQ], Rd[SQ], Horb[81], M[SQ];

    const int bfF = g_bf[isOnsite ? 1 : 0];
    const int bfR = g_bf[2];

    int src, dst;
    if (isOnsite) { src = e; dst = e; }
    else          { src = g_eidx[e]; dst = g_eidx[EE + e]; }   // clamped

    for (int t = threadIdx.x; t < SQ; t += blockDim.x) {
        Rs[t] = loadF(R, (long long)src * SQ + t, bfR);
        Rd[t] = loadF(R, (long long)dst * SQ + t, bfR);
    }
    for (int t = threadIdx.x; t < 81; t += blockDim.x) {
        int po = t / 9, qo = t % 9, p; float f;
        featmap(po, qo, &p, &f);
        Horb[t] = (p >= 0) ? f * loadF(feats, (long long)e * PP + p, bfF) : 0.f;
    }
    __syncthreads();

    for (int t = threadIdx.x; t < SQ; t += blockDim.x) {
        int i = t / SS, q = t % SS;
        int qo = q >> 1, sq = q & 1;
        float m = 0.f;
        for (int po = 0; po < 9; ++po)
            m += Rs[i * SS + 2 * po + sq] * Horb[po * 9 + qo];
        M[i * SS + q] = m;
    }
    __syncthreads();

    float* outp = isOnsite ? g_onRot : g_hopRot;
    for (int t = threadIdx.x; t < SQ; t += blockDim.x) {
        int i = t / SS, j = t % SS;
        float o = 0.f;
        for (int q = 0; q < SS; ++q)
            o += M[i * SS + q] * Rd[j * SS + q];
        outp[(long long)e * SQ + t] = o;
    }
}

// Store-once dense assembly. mode 0: interleaved complex floats (2*OUTC).
// mode 1: real part only, OUTC floats. Full coverage of [0, OUTC) cIdx.
__global__ void k_hk(float* out, int mode) {
    const int bid = blockIdx.x;
    const int pair = bid / KK, k = bid % KK;
    const int pa = pair / AA, pb = pair % AA;
    const int pairT = pb * AA + pa;
    const int offD = g_off[pair],  cntD = g_cnt[pair];
    const int offT = g_off[pairT], cntT = g_cnt[pairT];

    for (int t = threadIdx.x; t < SQ; t += blockDim.x) {
        const int i = t / SS, j = t % SS;
        float re = 0.f, im = 0.f;

        for (int l = 0; l < cntD; ++l) {             // direct: ph * hop[e][i,j]
            int e = g_list[offD + l];
            float v = g_hopRot[(long long)e * SQ + t];
            float c = g_phc[e * KK + k], s = g_phs[e * KK + k];
            re += v * c;
            im += v * s;
        }
        for (int l = 0; l < cntT; ++l) {             // reverse: conj(ph) * hop[e][j,i]
            int e = g_list[offT + l];
            float v = g_hopRot[(long long)e * SQ + j * SS + i];
            float c = g_phc[e * KK + k], s = g_phs[e * KK + k];
            re += v * c;
            im -= v * s;
        }
        if (pa == pb)                                // onsite + onsite^T (real)
            re += g_onRot[(long long)pa * SQ + i * SS + j]
                + g_onRot[(long long)pa * SQ + j * SS + i];

        const long long row = (long long)pa * SS + i;
        const long long col = (long long)pb * SS + j;
        const long long cIdx = ((long long)k * NN + row) * NN + col;  // < OUTC
        if (mode == 0) {
            out[2 * cIdx]     = re;
            out[2 * cIdx + 1] = im;
        } else {
            out[cIdx] = re;
        }
    }
}

extern "C" void kernel_launch(void* const* d_in, const int* in_sizes, int n_in,
                              void* d_out, int out_size) {
    // Logical element counts: hop, onsite, R, kpoints, shift, edge_index
    const long long elemSz[6] = { (long long)EE * PP, (long long)AA * PP,
                                  (long long)AA * SQ, KK * 3, EE * 3, 2 * EE };
    const void* ptr[6] = { 0, 0, 0, 0, 0, 0 };

    int nin = n_in;
    if (nin < 0)  nin = 0;
    if (nin > 32) nin = 32;

    int matched = 1;
    for (int s = 0; s < 6 && matched; ++s) {
        int found = 0;
        for (int i = 0; i < nin && !found; ++i)
            if ((long long)in_sizes[i] == elemSz[s]) { ptr[s] = d_in[i]; found = 1; }
        matched = found;
    }

    float* out = (float*)d_out;
    const long long os = (long long)out_size;

    // Output mode: write EXACTLY os floats in recognized worlds.
    int mode;
    if (os == 2 * OUTC)       mode = 0;   // float32 view of complex (interleaved)
    else if (os == 8 * OUTC)  mode = 0;   // byte count of complex buffer
    else if (os == OUTC)      mode = 1;   // float32 real-part world (or safe half-fill)
    else                      mode = -1;

    if (!matched || mode < 0) {
        // Diagnostic-safe: os/4 floats = at most os bytes, valid under any
        // dtype >= 1 byte/element.
        long long nz = os / 4;
        if (nz > 2 * OUTC) nz = 2 * OUTC;
        if (nz < 0) nz = 0;
        k_zero<<<4096, 512>>>(out, nz);
        return;
    }

    const void* hop   = ptr[0];
    const void* ons   = ptr[1];
    const void* R     = ptr[2];
    const void* kpts  = ptr[3];
    const void* shift = ptr[4];
    const unsigned int* eidxR = (const unsigned int*)ptr[5];

    k_detect<<<1, 512>>>(hop, ons, R, kpts, shift, eidxR);
    k_clr<<<(NPAIR + 511) / 512, 512>>>();
    k_count<<<(EE + 511) / 512, 512>>>();
    k_scan<<<1, 512>>>();
    k_fill<<<(EE + 511) / 512, 512>>>();
    k_phase<<<(EE * KK + 511) / 512, 512>>>(kpts, shift);
    k_rotate<<<EE, 512>>>(hop, R, 0);
    k_rotate<<<AA, 512>>>(ons, R, 1);
    k_hk<<<NPAIR * KK, 512>>>(out, mode);   // covers every output element once
}

// round 13
// speedup vs baseline: 1.9384x; 1.9384x over previous
#include <cuda_runtime.h>
#include <cuda_bf16.h>

// Problem constants (single species, e3tb 1s+1p+1d, K=4, A=192, E=3072)
#define AA 192
#define EE 3072
#define KK 4
#define PP 58
#define SS 18                          // spin_deg * norb
#define SQ (SS*SS)                     // 324
#define NN (AA*SS)                     // 3456
#define NPAIR (AA*AA)                  // 36864
#define OUTC ((long long)KK*NN*NN)     // complex64 elements = 47,775,744

// Scratch (__device__ globals)
__device__ float g_hopRot[EE * SQ];
__device__ float g_hopT  [EE * SQ];    // transposed copy for coalesced conj path
__device__ float g_onRot [AA * SQ];
__device__ int   g_eidx  [2 * EE];
__device__ int   g_cnt   [NPAIR];
__device__ int   g_off   [NPAIR];
__device__ int   g_cur   [NPAIR];
__device__ int   g_list  [EE];
__device__ float g_phc   [EE * KK];
__device__ float g_phs   [EE * KK];
__device__ int   g_bf    [5];          // per-float-buffer bf16 flag
__device__ int   g_is64;

// ---------------------------------------------------------------------------
__device__ __forceinline__ float loadF(const void* p, long long i, int bf) {
    if (bf) return __bfloat162float(((const __nv_bfloat16*)p)[i]);
    return ((const float*)p)[i];
}

__global__ void k_zero(float* p, long long nFloats) {
    long long i = (long long)blockIdx.x * blockDim.x + threadIdx.x;
    long long st = (long long)gridDim.x * blockDim.x;
    while (i < nFloats) { p[i] = 0.0f; i += st; }
}

// Detect dtypes (f32 vs bf16 per float buffer; int32 vs int64 for edge_index)
// and normalize edge_index. All reads stay within provably-present words.
__global__ void k_detect(const void* hop, const void* ons, const void* Rm,
                         const void* kp, const void* sh,
                         const unsigned int* eidx) {
    __shared__ int cnt[5];
    __shared__ int nz;
    const int t = threadIdx.x;   // 512
    if (t < 5) cnt[t] = 0;
    if (t == 0) nz = 0;
    __syncthreads();

    const void* bufs[5] = { hop, ons, Rm, kp, sh };
    const long long nels[5] = { (long long)EE * PP, (long long)AA * PP,
                                (long long)AA * SQ, KK * 3, EE * 3 };
    if (t < 256) {
        for (int b = 0; b < 5; ++b) {
            long long maxW = nels[b] / 2;            // words present under bf16 or f32
            long long w = ((long long)t * maxW) / 256;
            if (w >= maxW) w = maxW - 1;
            if (w < 0) w = 0;
            unsigned int word = ((const unsigned int*)bufs[b])[w];
            int m = (int)((word >> 8) & 0x7F);       // bf16: sign-stripped exponent bits
            if (m >= 0x35 && m <= 0x44) atomicAdd(&cnt[b], 1);
        }
    }
    int local = 0;
    for (int w = 1 + 2 * t; w < 2 * EE; w += 2 * 512)
        if (eidx[w] != 0u) local = 1;                // int64 in [0,192): odd words 0
    if (local) atomicOr(&nz, 1);
    __syncthreads();

    if (t < 5) g_bf[t] = (cnt[t] >= 64) ? 1 : 0;     // ambiguous => bf16 (never overreads)
    const int is64 = (nz == 0);
    if (t == 0) g_is64 = is64;
    for (int n = t; n < 2 * EE; n += 512) {
        int v = is64 ? (int)eidx[2 * n] : (int)eidx[n];
        if (v < 0) v = 0;
        if (v >= AA) v = AA - 1;
        g_eidx[n] = v;
    }
}

__global__ void k_clr() {
    int i = blockIdx.x * blockDim.x + threadIdx.x;
    if (i < NPAIR) { g_cnt[i] = 0; g_cur[i] = 0; }
}
__global__ void k_count() {
    int e = blockIdx.x * blockDim.x + threadIdx.x;
    if (e < EE) atomicAdd(&g_cnt[g_eidx[e] * AA + g_eidx[EE + e]], 1);
}
// Exclusive prefix sum over NPAIR counters: per-thread chunk sums + parallel
// Hillis-Steele over 512 partials (replaces 39.6us serial-thread0 version).
__global__ void k_scan() {
    __shared__ int part[512];
    const int T = 512, CHUNK = NPAIR / T;   // 72
    const int tid = threadIdx.x;
    const int base = tid * CHUNK;
    int s = 0;
    for (int i = 0; i < CHUNK; ++i) s += g_cnt[base + i];
    part[tid] = s;
    __syncthreads();
    for (int d = 1; d < T; d <<= 1) {
        int v = (tid >= d) ? part[tid - d] : 0;
        __syncthreads();
        part[tid] += v;
        __syncthreads();
    }
    int acc = (tid == 0) ? 0 : part[tid - 1];   // exclusive
    for (int i = 0; i < CHUNK; ++i) { g_off[base + i] = acc; acc += g_cnt[base + i]; }
}
__global__ void k_fill() {
    int e = blockIdx.x * blockDim.x + threadIdx.x;
    if (e < EE) {
        int pair = g_eidx[e] * AA + g_eidx[EE + e];
        int pos = g_off[pair] + atomicAdd(&g_cur[pair], 1);
        if (pos >= 0 && pos < EE) g_list[pos] = e;
    }
}

__global__ void k_phase(const void* kpts, const void* shift) {
    int idx = blockIdx.x * blockDim.x + threadIdx.x;
    if (idx < EE * KK) {
        const int bfK = g_bf[3], bfS = g_bf[4];
        int e = idx / KK, k = idx % KK;
        float d = 0.f;
        for (int c = 0; c < 3; ++c)
            d += loadF(kpts, k * 3 + c, bfK) * loadF(shift, e * 3 + c, bfS);
        float sn, cs;
        sincosf(-6.283185307179586f * d, &sn, &cs);   // exp(-2*pi*i*d)
        g_phc[idx] = cs;
        g_phs[idx] = sn;
    }
}

__device__ void featmap(int po, int qo, int* p, float* f) {
    int bi = (po == 0) ? 0 : (po < 4 ? 1 : 2);
    int bj = (qo == 0) ? 0 : (qo < 4 ? 1 : 2);
    if (bi > bj) { *p = -1; *f = 0.f; return; }
    *f = (bi == bj) ? 0.5f : 1.0f;
    int ri = po - (bi == 0 ? 0 : (bi == 1 ? 1 : 4));
    int ci = qo - (bj == 0 ? 0 : (bj == 1 ? 1 : 4));
    int jo = (bj == 0 ? 1 : (bj == 1 ? 3 : 5));
    int b;
    if (bi == 0)      b = (bj == 0) ? 0 : (bj == 1 ? 1 : 4);
    else if (bi == 1) b = (bj == 1) ? 9 : 18;
    else              b = 33;
    *p = b + ri * jo + ci;
}

// out = Rs @ H2 @ Rd^T (spin-interleaved doubling). Hop edges also emit a
// transposed copy (from smem) so the conj path in k_hk reads coalesced.
__global__ void k_rotate(const void* feats, const void* R, int isOnsite) {
    const int e = blockIdx.x;
    __shared__ float Rs[SQ], Rd[SQ], Horb[81], M[SQ], O[SQ];

    const int bfF = g_bf[isOnsite ? 1 : 0];
    const int bfR = g_bf[2];

    int src, dst;
    if (isOnsite) { src = e; dst = e; }
    else          { src = g_eidx[e]; dst = g_eidx[EE + e]; }

    for (int t = threadIdx.x; t < SQ; t += blockDim.x) {
        Rs[t] = loadF(R, (long long)src * SQ + t, bfR);
        Rd[t] = loadF(R, (long long)dst * SQ + t, bfR);
    }
    for (int t = threadIdx.x; t < 81; t += blockDim.x) {
        int po = t / 9, qo = t % 9, p; float f;
        featmap(po, qo, &p, &f);
        Horb[t] = (p >= 0) ? f * loadF(feats, (long long)e * PP + p, bfF) : 0.f;
    }
    __syncthreads();

    for (int t = threadIdx.x; t < SQ; t += blockDim.x) {
        int i = t / SS, q = t % SS;
        int qo = q >> 1, sq = q & 1;
        float m = 0.f;
        for (int po = 0; po < 9; ++po)
            m += Rs[i * SS + 2 * po + sq] * Horb[po * 9 + qo];
        M[i * SS + q] = m;
    }
    __syncthreads();

    for (int t = threadIdx.x; t < SQ; t += blockDim.x) {
        int i = t / SS, j = t % SS;
        float o = 0.f;
        for (int q = 0; q < SS; ++q)
            o += M[i * SS + q] * Rd[j * SS + q];
        O[t] = o;
    }
    __syncthreads();

    if (isOnsite) {
        for (int t = threadIdx.x; t < SQ; t += blockDim.x)
            g_onRot[(long long)e * SQ + t] = O[t];
    } else {
        for (int t = threadIdx.x; t < SQ; t += blockDim.x) {
            int i = t / SS, j = t % SS;
            g_hopRot[(long long)e * SQ + t] = O[t];
            g_hopT  [(long long)e * SQ + t] = O[j * SS + i];   // coalesced store
        }
    }
}

// Store-once dense assembly, all KK k-planes fused per block.
// grid = NPAIR, block = 324 (one thread per (i,j)). Hop values loaded once per
// edge; phases are uniform broadcast loads. float2 stores (8B) per k-plane.
__global__ void k_hk(float* out, int mode) {
    const int pair = blockIdx.x;
    const int pa = pair / AA, pb = pair % AA;
    const int pairT = pb * AA + pa;
    const int offD = g_off[pair],  cntD = g_cnt[pair];
    const int offT = g_off[pairT], cntT = g_cnt[pairT];
    const int t = threadIdx.x;            // 0..323
    const int i = t / SS, j = t % SS;

    float re[KK], im[KK];
#pragma unroll
    for (int k = 0; k < KK; ++k) { re[k] = 0.f; im[k] = 0.f; }

    for (int l = 0; l < cntD; ++l) {      // direct: ph * hop[e][i,j]
        int e = g_list[offD + l];
        float v = g_hopRot[(long long)e * SQ + t];
#pragma unroll
        for (int k = 0; k < KK; ++k) {
            float c = g_phc[e * KK + k], s = g_phs[e * KK + k];
            re[k] += v * c;
            im[k] += v * s;
        }
    }
    for (int l = 0; l < cntT; ++l) {      // reverse: conj(ph) * hop[e][j,i]
        int e = g_list[offT + l];
        float v = g_hopT[(long long)e * SQ + t];
#pragma unroll
        for (int k = 0; k < KK; ++k) {
            float c = g_phc[e * KK + k], s = g_phs[e * KK + k];
            re[k] += v * c;
            im[k] -= v * s;
        }
    }
    if (pa == pb) {                       // onsite + onsite^T (real, k-indep)
        float v = g_onRot[(long long)pa * SQ + i * SS + j]
                + g_onRot[(long long)pa * SQ + j * SS + i];
#pragma unroll
        for (int k = 0; k < KK; ++k) re[k] += v;
    }

    const long long row = (long long)pa * SS + i;
    const long long col = (long long)pb * SS + j;
    const long long base = row * NN + col;
    if (mode == 0) {
#pragma unroll
        for (int k = 0; k < KK; ++k) {
            long long cIdx = (long long)k * NN * NN + base;
            *(float2*)(out + 2 * cIdx) = make_float2(re[k], im[k]);
        }
    } else {
#pragma unroll
        for (int k = 0; k < KK; ++k)
            out[(long long)k * NN * NN + base] = re[k];
    }
}

extern "C" void kernel_launch(void* const* d_in, const int* in_sizes, int n_in,
                              void* d_out, int out_size) {
    // Logical element counts: hop, onsite, R, kpoints, shift, edge_index
    const long long elemSz[6] = { (long long)EE * PP, (long long)AA * PP,
                                  (long long)AA * SQ, KK * 3, EE * 3, 2 * EE };
    const void* ptr[6] = { 0, 0, 0, 0, 0, 0 };

    int nin = n_in;
    if (nin < 0)  nin = 0;
    if (nin > 32) nin = 32;

    int matched = 1;
    for (int s = 0; s < 6 && matched; ++s) {
        int found = 0;
        for (int i = 0; i < nin && !found; ++i)
            if ((long long)in_sizes[i] == elemSz[s]) { ptr[s] = d_in[i]; found = 1; }
        matched = found;
    }

    float* out = (float*)d_out;
    const long long os = (long long)out_size;

    int mode;
    if (os == 2 * OUTC)       mode = 0;   // float32 view of complex (interleaved)
    else if (os == 8 * OUTC)  mode = 0;   // bytes of complex buffer
    else if (os == OUTC)      mode = 1;   // real-part-only world (safe half-fill)
    else                      mode = -1;

    if (!matched || mode < 0) {
        long long nz = os / 4;
        if (nz > 2 * OUTC) nz = 2 * OUTC;
        if (nz < 0) nz = 0;
        k_zero<<<4096, 512>>>(out, nz);
        return;
    }

    const void* hop   = ptr[0];
    const void* ons   = ptr[1];
    const void* R     = ptr[2];
    const void* kpts  = ptr[3];
    const void* shift = ptr[4];
    const unsigned int* eidxR = (const unsigned int*)ptr[5];

    k_detect<<<1, 512>>>(hop, ons, R, kpts, shift, eidxR);
    k_clr<<<(NPAIR + 511) / 512, 512>>>();
    k_count<<<(EE + 511) / 512, 512>>>();
    k_scan<<<1, 512>>>();
    k_fill<<<(EE + 511) / 512, 512>>>();
    k_phase<<<(EE * KK + 511) / 512, 512>>>(kpts, shift);
    k_rotate<<<EE, 512>>>(hop, R, 0);
    k_rotate<<<AA, 512>>>(ons, R, 1);
    k_hk<<<NPAIR, SQ>>>(out, mode);   // every output element stored exactly once
}

// round 14
// speedup vs baseline: 2.1431x; 1.1056x over previous
#include <cuda_runtime.h>
#include <cuda_bf16.h>

// Problem constants (single species, e3tb 1s+1p+1d, K=4, A=192, E=3072)
#define AA 192
#define EE 3072
#define KK 4
#define PP 58
#define SS 18                          // spin_deg * norb
#define SQ (SS*SS)                     // 324
#define NN (AA*SS)                     // 3456
#define NPAIR (AA*AA)                  // 36864
#define OUTC ((long long)KK*NN*NN)     // complex64 elements = 47,775,744

// Scratch (__device__ globals)
__device__ float g_hopRot[EE * SQ];
__device__ float g_hopT  [EE * SQ];    // transposed copy for coalesced conj path
__device__ float g_onRot [AA * SQ];
__device__ int   g_eidx  [2 * EE];
__device__ int   g_head  [NPAIR];      // per-pair linked list head (-1 = empty)
__device__ int   g_next  [EE];         // chain links
__device__ float g_phc   [EE * KK];
__device__ float g_phs   [EE * KK];
__device__ int   g_bf    [5];          // per-float-buffer bf16 flag
__device__ int   g_is64;

// ---------------------------------------------------------------------------
__device__ __forceinline__ float loadF(const void* p, long long i, int bf) {
    if (bf) return __bfloat162float(((const __nv_bfloat16*)p)[i]);
    return ((const float*)p)[i];
}

__global__ void k_zero(float* p, long long nFloats) {
    long long i = (long long)blockIdx.x * blockDim.x + threadIdx.x;
    long long st = (long long)gridDim.x * blockDim.x;
    while (i < nFloats) { p[i] = 0.0f; i += st; }
}

// Detect dtypes (f32 vs bf16 per float buffer; int32 vs int64 for edge_index)
// and normalize edge_index. All reads stay within provably-present words.
__global__ void k_detect(const void* hop, const void* ons, const void* Rm,
                         const void* kp, const void* sh,
                         const unsigned int* eidx) {
    __shared__ int cnt[5];
    __shared__ int nz;
    const int t = threadIdx.x;   // 512
    if (t < 5) cnt[t] = 0;
    if (t == 0) nz = 0;
    __syncthreads();

    const void* bufs[5] = { hop, ons, Rm, kp, sh };
    const long long nels[5] = { (long long)EE * PP, (long long)AA * PP,
                                (long long)AA * SQ, KK * 3, EE * 3 };
    if (t < 256) {
        for (int b = 0; b < 5; ++b) {
            long long maxW = nels[b] / 2;            // words present under bf16 or f32
            long long w = ((long long)t * maxW) / 256;
            if (w >= maxW) w = maxW - 1;
            if (w < 0) w = 0;
            unsigned int word = ((const unsigned int*)bufs[b])[w];
            int m = (int)((word >> 8) & 0x7F);       // bf16: sign-stripped exponent bits
            if (m >= 0x35 && m <= 0x44) atomicAdd(&cnt[b], 1);
        }
    }
    int local = 0;
    for (int w = 1 + 2 * t; w < 2 * EE; w += 2 * 512)
        if (eidx[w] != 0u) local = 1;                // int64 in [0,192): odd words 0
    if (local) atomicOr(&nz, 1);
    __syncthreads();

    if (t < 5) g_bf[t] = (cnt[t] >= 64) ? 1 : 0;     // ambiguous => bf16 (never overreads)
    const int is64 = (nz == 0);
    if (t == 0) g_is64 = is64;
    for (int n = t; n < 2 * EE; n += 512) {
        int v = is64 ? (int)eidx[2 * n] : (int)eidx[n];
        if (v < 0) v = 0;
        if (v >= AA) v = AA - 1;
        g_eidx[n] = v;
    }
}

__global__ void k_clr() {
    int i = blockIdx.x * blockDim.x + threadIdx.x;
    if (i < NPAIR) g_head[i] = -1;
}

// Bin edges by pair via lock-free linked-list push (replaces count+scan+fill).
__global__ void k_fill() {
    int e = blockIdx.x * blockDim.x + threadIdx.x;
    if (e < EE) {
        int pair = g_eidx[e] * AA + g_eidx[EE + e];
        g_next[e] = atomicExch(&g_head[pair], e);
    }
}

__global__ void k_phase(const void* kpts, const void* shift) {
    int idx = blockIdx.x * blockDim.x + threadIdx.x;
    if (idx < EE * KK) {
        const int bfK = g_bf[3], bfS = g_bf[4];
        int e = idx / KK, k = idx % KK;
        float d = 0.f;
        for (int c = 0; c < 3; ++c)
            d += loadF(kpts, k * 3 + c, bfK) * loadF(shift, e * 3 + c, bfS);
        float sn, cs;
        sincosf(-6.283185307179586f * d, &sn, &cs);   // exp(-2*pi*i*d)
        g_phc[idx] = cs;
        g_phs[idx] = sn;
    }
}

__device__ void featmap(int po, int qo, int* p, float* f) {
    int bi = (po == 0) ? 0 : (po < 4 ? 1 : 2);
    int bj = (qo == 0) ? 0 : (qo < 4 ? 1 : 2);
    if (bi > bj) { *p = -1; *f = 0.f; return; }
    *f = (bi == bj) ? 0.5f : 1.0f;
    int ri = po - (bi == 0 ? 0 : (bi == 1 ? 1 : 4));
    int ci = qo - (bj == 0 ? 0 : (bj == 1 ? 1 : 4));
    int jo = (bj == 0 ? 1 : (bj == 1 ? 3 : 5));
    int b;
    if (bi == 0)      b = (bj == 0) ? 0 : (bj == 1 ? 1 : 4);
    else if (bi == 1) b = (bj == 1) ? 9 : 18;
    else              b = 33;
    *p = b + ri * jo + ci;
}

// out = Rs @ H2 @ Rd^T (spin-interleaved doubling). Hop edges also emit a
// transposed copy (from smem) so the conj path in k_hk reads coalesced.
__global__ void k_rotate(const void* feats, const void* R, int isOnsite) {
    const int e = blockIdx.x;
    __shared__ float Rs[SQ], Rd[SQ], Horb[81], M[SQ], O[SQ];

    const int bfF = g_bf[isOnsite ? 1 : 0];
    const int bfR = g_bf[2];

    int src, dst;
    if (isOnsite) { src = e; dst = e; }
    else          { src = g_eidx[e]; dst = g_eidx[EE + e]; }

    for (int t = threadIdx.x; t < SQ; t += blockDim.x) {
        Rs[t] = loadF(R, (long long)src * SQ + t, bfR);
        Rd[t] = loadF(R, (long long)dst * SQ + t, bfR);
    }
    for (int t = threadIdx.x; t < 81; t += blockDim.x) {
        int po = t / 9, qo = t % 9, p; float f;
        featmap(po, qo, &p, &f);
        Horb[t] = (p >= 0) ? f * loadF(feats, (long long)e * PP + p, bfF) : 0.f;
    }
    __syncthreads();

    for (int t = threadIdx.x; t < SQ; t += blockDim.x) {
        int i = t / SS, q = t % SS;
        int qo = q >> 1, sq = q & 1;
        float m = 0.f;
        for (int po = 0; po < 9; ++po)
            m += Rs[i * SS + 2 * po + sq] * Horb[po * 9 + qo];
        M[i * SS + q] = m;
    }
    __syncthreads();

    for (int t = threadIdx.x; t < SQ; t += blockDim.x) {
        int i = t / SS, j = t % SS;
        float o = 0.f;
        for (int q = 0; q < SS; ++q)
            o += M[i * SS + q] * Rd[j * SS + q];
        O[t] = o;
    }
    __syncthreads();

    if (isOnsite) {
        for (int t = threadIdx.x; t < SQ; t += blockDim.x)
            g_onRot[(long long)e * SQ + t] = O[t];
    } else {
        for (int t = threadIdx.x; t < SQ; t += blockDim.x) {
            int i = t / SS, j = t % SS;
            g_hopRot[(long long)e * SQ + t] = O[t];
            g_hopT  [(long long)e * SQ + t] = O[j * SS + i];   // coalesced store
        }
    }
}

// Store-once dense assembly, all KK k-planes fused per block. Edge sets come
// from per-pair linked lists (uniform broadcast walks, ~0.08 edges/pair avg).
// Streaming stores (__stcs): output is written once, never re-read.
__global__ void k_hk(float* out, int mode) {
    const int pair = blockIdx.x;
    const int pa = pair / AA, pb = pair % AA;
    const int pairT = pb * AA + pa;
    const int t = threadIdx.x;            // 0..323
    const int i = t / SS, j = t % SS;

    float re[KK], im[KK];
#pragma unroll
    for (int k = 0; k < KK; ++k) { re[k] = 0.f; im[k] = 0.f; }

    for (int e = g_head[pair]; e >= 0; e = g_next[e]) {    // direct: ph * hop[e][i,j]
        float v = g_hopRot[(long long)e * SQ + t];
#pragma unroll
        for (int k = 0; k < KK; ++k) {
            float c = g_phc[e * KK + k], s = g_phs[e * KK + k];
            re[k] += v * c;
            im[k] += v * s;
        }
    }
    for (int e = g_head[pairT]; e >= 0; e = g_next[e]) {   // reverse: conj(ph)*hop[e][j,i]
        float v = g_hopT[(long long)e * SQ + t];
#pragma unroll
        for (int k = 0; k < KK; ++k) {
            float c = g_phc[e * KK + k], s = g_phs[e * KK + k];
            re[k] += v * c;
            im[k] -= v * s;
        }
    }
    if (pa == pb) {                       // onsite + onsite^T (real, k-indep)
        float v = g_onRot[(long long)pa * SQ + i * SS + j]
                + g_onRot[(long long)pa * SQ + j * SS + i];
#pragma unroll
        for (int k = 0; k < KK; ++k) re[k] += v;
    }

    const long long row = (long long)pa * SS + i;
    const long long col = (long long)pb * SS + j;
    const long long base = row * NN + col;
    if (mode == 0) {
#pragma unroll
        for (int k = 0; k < KK; ++k) {
            long long cIdx = (long long)k * NN * NN + base;
            __stcs((float2*)(out + 2 * cIdx), make_float2(re[k], im[k]));
        }
    } else {
#pragma unroll
        for (int k = 0; k < KK; ++k)
            __stcs(out + (long long)k * NN * NN + base, re[k]);
    }
}

extern "C" void kernel_launch(void* const* d_in, const int* in_sizes, int n_in,
                              void* d_out, int out_size) {
    // Logical element counts: hop, onsite, R, kpoints, shift, edge_index
    const long long elemSz[6] = { (long long)EE * PP, (long long)AA * PP,
                                  (long long)AA * SQ, KK * 3, EE * 3, 2 * EE };
    const void* ptr[6] = { 0, 0, 0, 0, 0, 0 };

    int nin = n_in;
    if (nin < 0)  nin = 0;
    if (nin > 32) nin = 32;

    int matched = 1;
    for (int s = 0; s < 6 && matched; ++s) {
        int found = 0;
        for (int i = 0; i < nin && !found; ++i)
            if ((long long)in_sizes[i] == elemSz[s]) { ptr[s] = d_in[i]; found = 1; }
        matched = found;
    }

    float* out = (float*)d_out;
    const long long os = (long long)out_size;

    int mode;
    if (os == 2 * OUTC)       mode = 0;   // float32 view of complex (interleaved)
    else if (os == 8 * OUTC)  mode = 0;   // bytes of complex buffer
    else if (os == OUTC)      mode = 1;   // real-part-only world (safe half-fill)
    else                      mode = -1;

    if (!matched || mode < 0) {
        long long nz = os / 4;
        if (nz > 2 * OUTC) nz = 2 * OUTC;
        if (nz < 0) nz = 0;
        k_zero<<<4096, 512>>>(out, nz);
        return;
    }

    const void* hop   = ptr[0];
    const void* ons   = ptr[1];
    const void* R     = ptr[2];
    const void* kpts  = ptr[3];
    const void* shift = ptr[4];
    const unsigned int* eidxR = (const unsigned int*)ptr[5];

    k_detect<<<1, 512>>>(hop, ons, R, kpts, shift, eidxR);
    k_clr<<<(NPAIR + 511) / 512, 512>>>();
    k_fill<<<(EE + 511) / 512, 512>>>();
    k_phase<<<(EE * KK + 511) / 512, 512>>>(kpts, shift);
    k_rotate<<<EE, 512>>>(hop, R, 0);
    k_rotate<<<AA, 512>>>(ons, R, 1);
    k_hk<<<NPAIR, SQ>>>(out, mode);   // every output element stored exactly once
}

// round 15
// speedup vs baseline: 3.5454x; 1.6543x over previous
#include <cuda_runtime.h>
#include <cuda_bf16.h>

// Problem constants (single species, e3tb 1s+1p+1d, K=4, A=192, E=3072)
#define AA 192
#define EE 3072
#define KK 4
#define PP 58
#define SS 18                          // spin_deg * norb
#define SQ (SS*SS)                     // 324
#define NN (AA*SS)                     // 3456
#define NPAIR (AA*AA)                  // 36864
#define OUTC ((long long)KK*NN*NN)     // complex64 elements = 47,775,744

// Scratch (__device__ globals)
__device__ float g_hopRot[EE * SQ];
__device__ float g_hopT  [EE * SQ];    // transposed copy for coalesced conj path
__device__ float g_onRot [AA * SQ];
__device__ int   g_eidx  [2 * EE];
__device__ int   g_head  [NPAIR];      // per-pair linked list head (-1 = empty)
__device__ int   g_next  [EE];         // chain links
__device__ float g_phc   [EE * KK];
__device__ float g_phs   [EE * KK];
__device__ int   g_bf    [5];          // per-float-buffer bf16 flag

// ---------------------------------------------------------------------------
__device__ __forceinline__ float loadF(const void* p, long long i, int bf) {
    if (bf) return __bfloat162float(((const __nv_bfloat16*)p)[i]);
    return ((const float*)p)[i];
}

__global__ void k_zero(float* p, long long nFloats) {
    long long i = (long long)blockIdx.x * blockDim.x + threadIdx.x;
    long long st = (long long)gridDim.x * blockDim.x;
    while (i < nFloats) { p[i] = 0.0f; i += st; }
}

// Detect dtypes (f32 vs bf16 per float buffer; int32 vs int64 for edge_index),
// normalize edge_index, AND clear the pair linked-list heads (fused k_clr).
// All reads stay within provably-present words.
__global__ void k_detect(const void* hop, const void* ons, const void* Rm,
                         const void* kp, const void* sh,
                         const unsigned int* eidx) {
    __shared__ int cnt[5];
    __shared__ int nz;
    const int t = threadIdx.x;   // 512
    if (t < 5) cnt[t] = 0;
    if (t == 0) nz = 0;
    // fused clr: 36864 heads, 72 per thread (independent of detection below)
    for (int i = t; i < NPAIR; i += 512) g_head[i] = -1;
    __syncthreads();

    const void* bufs[5] = { hop, ons, Rm, kp, sh };
    const long long nels[5] = { (long long)EE * PP, (long long)AA * PP,
                                (long long)AA * SQ, KK * 3, EE * 3 };
    if (t < 256) {
        for (int b = 0; b < 5; ++b) {
            long long maxW = nels[b] / 2;            // words present under bf16 or f32
            long long w = ((long long)t * maxW) / 256;
            if (w >= maxW) w = maxW - 1;
            if (w < 0) w = 0;
            unsigned int word = ((const unsigned int*)bufs[b])[w];
            int m = (int)((word >> 8) & 0x7F);       // bf16: sign-stripped exponent bits
            if (m >= 0x35 && m <= 0x44) atomicAdd(&cnt[b], 1);
        }
    }
    int local = 0;
    for (int w = 1 + 2 * t; w < 2 * EE; w += 2 * 512)
        if (eidx[w] != 0u) local = 1;                // int64 in [0,192): odd words 0
    if (local) atomicOr(&nz, 1);
    __syncthreads();

    if (t < 5) g_bf[t] = (cnt[t] >= 64) ? 1 : 0;     // ambiguous => bf16 (never overreads)
    const int is64 = (nz == 0);
    for (int n = t; n < 2 * EE; n += 512) {
        int v = is64 ? (int)eidx[2 * n] : (int)eidx[n];
        if (v < 0) v = 0;
        if (v >= AA) v = AA - 1;
        g_eidx[n] = v;
    }
}

__device__ void featmap(int po, int qo, int* p, float* f) {
    int bi = (po == 0) ? 0 : (po < 4 ? 1 : 2);
    int bj = (qo == 0) ? 0 : (qo < 4 ? 1 : 2);
    if (bi > bj) { *p = -1; *f = 0.f; return; }
    *f = (bi == bj) ? 0.5f : 1.0f;
    int ri = po - (bi == 0 ? 0 : (bi == 1 ? 1 : 4));
    int ci = qo - (bj == 0 ? 0 : (bj == 1 ? 1 : 4));
    int jo = (bj == 0 ? 1 : (bj == 1 ? 3 : 5));
    int b;
    if (bi == 0)      b = (bj == 0) ? 0 : (bj == 1 ? 1 : 4);
    else if (bi == 1) b = (bj == 1) ? 9 : 18;
    else              b = 33;
    *p = b + ri * jo + ci;
}

// Fused rotate: grid = EE + AA blocks of 324 threads.
//   blocks [0, EE):   hop edges — rotate + transposed copy + Bloch phases
//                     (threads 0..3) + linked-list fill (thread 0)
//   blocks [EE, +AA): onsite — rotate only
// out = Rs @ H2 @ Rd^T with spin-interleaved doubling H2[2po+s,2qo+s]=Horb[po,qo].
__global__ void k_rotate(const void* feats, const void* ons,
                         const void* R, const void* kpts, const void* shift) {
    const int isOnsite = (blockIdx.x >= EE);
    const int e = isOnsite ? (blockIdx.x - EE) : blockIdx.x;
    const int t = threadIdx.x;   // 0..323
    __shared__ float Rs[SQ], Rd[SQ], Horb[81], M[SQ], O[SQ];

    const int bfF = g_bf[isOnsite ? 1 : 0];
    const int bfR = g_bf[2];
    const void* f = isOnsite ? ons : feats;

    int src, dst;
    if (isOnsite) { src = e; dst = e; }
    else          { src = g_eidx[e]; dst = g_eidx[EE + e]; }   // clamped

    Rs[t] = loadF(R, (long long)src * SQ + t, bfR);
    Rd[t] = loadF(R, (long long)dst * SQ + t, bfR);
    if (t < 81) {
        int po = t / 9, qo = t % 9, p; float fac;
        featmap(po, qo, &p, &fac);
        Horb[t] = (p >= 0) ? fac * loadF(f, (long long)e * PP + p, bfF) : 0.f;
    }
    if (!isOnsite) {
        if (t < KK) {   // Bloch phase exp(-2*pi*i k.S_e)
            const int bfK = g_bf[3], bfS = g_bf[4];
            float d = 0.f;
            for (int c = 0; c < 3; ++c)
                d += loadF(kpts, t * 3 + c, bfK) * loadF(shift, e * 3 + c, bfS);
            float sn, cs;
            sincosf(-6.283185307179586f * d, &sn, &cs);
            g_phc[e * KK + t] = cs;
            g_phs[e * KK + t] = sn;
        }
        if (t == 0) {   // pair binning via lock-free list push
            int pair = src * AA + dst;
            g_next[e] = atomicExch(&g_head[pair], e);
        }
    }
    __syncthreads();

    {   // Stage 1: M[i,q] = sum_po Rs[i, 2po+sq] * Horb[po, qo], q = 2qo+sq
        int i = t / SS, q = t % SS;
        int qo = q >> 1, sq = q & 1;
        float m = 0.f;
#pragma unroll
        for (int po = 0; po < 9; ++po)
            m += Rs[i * SS + 2 * po + sq] * Horb[po * 9 + qo];
        M[i * SS + q] = m;
    }
    __syncthreads();

    {   // Stage 2: O[i,j] = sum_q M[i,q] * Rd[j,q]
        int i = t / SS, j = t % SS;
        float o = 0.f;
#pragma unroll
        for (int q = 0; q < SS; ++q)
            o += M[i * SS + q] * Rd[j * SS + q];
        O[t] = o;
    }
    __syncthreads();

    if (isOnsite) {
        g_onRot[(long long)e * SQ + t] = O[t];
    } else {
        int i = t / SS, j = t % SS;
        g_hopRot[(long long)e * SQ + t] = O[t];
        g_hopT  [(long long)e * SQ + t] = O[j * SS + i];   // coalesced store
    }
}

// Store-once dense assembly, all KK k-planes fused per block. Edge sets come
// from per-pair linked lists (uniform broadcast walks, ~0.08 edges/pair avg).
// Streaming stores (__stcs): output is written once, never re-read.
__global__ void k_hk(float* out, int mode) {
    const int pair = blockIdx.x;
    const int pa = pair / AA, pb = pair % AA;
    const int pairT = pb * AA + pa;
    const int t = threadIdx.x;            // 0..323
    const int i = t / SS, j = t % SS;

    float re[KK], im[KK];
#pragma unroll
    for (int k = 0; k < KK; ++k) { re[k] = 0.f; im[k] = 0.f; }

    for (int e = g_head[pair]; e >= 0; e = g_next[e]) {    // direct: ph * hop[e][i,j]
        float v = g_hopRot[(long long)e * SQ + t];
#pragma unroll
        for (int k = 0; k < KK; ++k) {
            float c = g_phc[e * KK + k], s = g_phs[e * KK + k];
            re[k] += v * c;
            im[k] += v * s;
        }
    }
    for (int e = g_head[pairT]; e >= 0; e = g_next[e]) {   // reverse: conj(ph)*hop[e][j,i]
        float v = g_hopT[(long long)e * SQ + t];
#pragma unroll
        for (int k = 0; k < KK; ++k) {
            float c = g_phc[e * KK + k], s = g_phs[e * KK + k];
            re[k] += v * c;
            im[k] -= v * s;
        }
    }
    if (pa == pb) {                       // onsite + onsite^T (real, k-indep)
        float v = g_onRot[(long long)pa * SQ + i * SS + j]
                + g_onRot[(long long)pa * SQ + j * SS + i];
#pragma unroll
        for (int k = 0; k < KK; ++k) re[k] += v;
    }

    const long long row = (long long)pa * SS + i;
    const long long col = (long long)pb * SS + j;
    const long long base = row * NN + col;
    if (mode == 0) {
#pragma unroll
        for (int k = 0; k < KK; ++k) {
            long long cIdx = (long long)k * NN * NN + base;
            __stcs((float2*)(out + 2 * cIdx), make_float2(re[k], im[k]));
        }
    } else {
#pragma unroll
        for (int k = 0; k < KK; ++k)
            __stcs(out + (long long)k * NN * NN + base, re[k]);
    }
}

extern "C" void kernel_launch(void* const* d_in, const int* in_sizes, int n_in,
                              void* d_out, int out_size) {
    // Logical element counts: hop, onsite, R, kpoints, shift, edge_index
    const long long elemSz[6] = { (long long)EE * PP, (long long)AA * PP,
                                  (long long)AA * SQ, KK * 3, EE * 3, 2 * EE };
    const void* ptr[6] = { 0, 0, 0, 0, 0, 0 };

    int nin = n_in;
    if (nin < 0)  nin = 0;
    if (nin > 32) nin = 32;

    int matched = 1;
    for (int s = 0; s < 6 && matched; ++s) {
        int found = 0;
        for (int i = 0; i < nin && !found; ++i)
            if ((long long)in_sizes[i] == elemSz[s]) { ptr[s] = d_in[i]; found = 1; }
        matched = found;
    }

    float* out = (float*)d_out;
    const long long os = (long long)out_size;

    int mode;
    if (os == 2 * OUTC)       mode = 0;   // float32 view of complex (interleaved)
    else if (os == 8 * OUTC)  mode = 0;   // bytes of complex buffer
    else if (os == OUTC)      mode = 1;   // real-part-only world (safe half-fill)
    else                      mode = -1;

    if (!matched || mode < 0) {
        long long nz = os / 4;
        if (nz > 2 * OUTC) nz = 2 * OUTC;
        if (nz < 0) nz = 0;
        k_zero<<<4096, 512>>>(out, nz);
        return;
    }

    const void* hop   = ptr[0];
    const void* ons   = ptr[1];
    const void* R     = ptr[2];
    const void* kpts  = ptr[3];
    const void* shift = ptr[4];
    const unsigned int* eidxR = (const unsigned int*)ptr[5];

    k_detect<<<1, 512>>>(hop, ons, R, kpts, shift, eidxR);     // + clr fused
    k_rotate<<<EE + AA, SQ>>>(hop, ons, R, kpts, shift);       // + phase + fill fused
    k_hk<<<NPAIR, SQ>>>(out, mode);   // every output element stored exactly once
}

// round 16
// speedup vs baseline: 3.6218x; 1.0216x over previous
#include <cuda_runtime.h>
#include <cuda_bf16.h>

// Problem constants (single species, e3tb 1s+1p+1d, K=4, A=192, E=3072)
#define AA 192
#define EE 3072
#define KK 4
#define PP 58
#define SS 18                          // spin_deg * norb
#define SQ (SS*SS)                     // 324
#define NN (AA*SS)                     // 3456
#define NPAIR (AA*AA)                  // 36864
#define OUTC ((long long)KK*NN*NN)     // complex64 elements = 47,775,744

// Scratch (__device__ globals)
__device__ float g_hopRot[EE * SQ];
__device__ float g_hopT  [EE * SQ];    // transposed copy for coalesced conj path
__device__ float g_onRot [AA * SQ];
__device__ int   g_eidx  [2 * EE];
__device__ int   g_head  [NPAIR];      // per-pair linked list head (-1 = empty)
__device__ int   g_next  [EE];         // chain links
__device__ float g_phc   [EE * KK];
__device__ float g_phs   [EE * KK];
__device__ int   g_bf    [5];          // per-float-buffer bf16 flag

// ---------------------------------------------------------------------------
__device__ __forceinline__ float loadF(const void* p, long long i, int bf) {
    if (bf) return __bfloat162float(((const __nv_bfloat16*)p)[i]);
    return ((const float*)p)[i];
}

__global__ void k_zero(float* p, long long nFloats) {
    long long i = (long long)blockIdx.x * blockDim.x + threadIdx.x;
    long long st = (long long)gridDim.x * blockDim.x;
    while (i < nFloats) { p[i] = 0.0f; i += st; }
}

// Parallelized detect: blocks >= 1 clear the 36864 list heads (grid-stride);
// block 0 does dtype sniffing (f32 vs bf16 per float buffer; int32 vs int64
// for edge_index) + edge_index normalization. All reads stay within
// provably-present words under either dtype.
__global__ void k_detect(const void* hop, const void* ons, const void* Rm,
                         const void* kp, const void* sh,
                         const unsigned int* eidx) {
    const int t = threadIdx.x;   // 512
    if (blockIdx.x != 0) {
        for (int i = (blockIdx.x - 1) * 512 + t; i < NPAIR; i += (gridDim.x - 1) * 512)
            g_head[i] = -1;
        return;
    }

    __shared__ int cnt[5];
    __shared__ int nz;
    if (t < 5) cnt[t] = 0;
    if (t == 0) nz = 0;
    __syncthreads();

    const void* bufs[5] = { hop, ons, Rm, kp, sh };
    const long long nels[5] = { (long long)EE * PP, (long long)AA * PP,
                                (long long)AA * SQ, KK * 3, EE * 3 };
    if (t < 256) {
        for (int b = 0; b < 5; ++b) {
            long long maxW = nels[b] / 2;            // words present under bf16 or f32
            long long w = ((long long)t * maxW) / 256;
            if (w >= maxW) w = maxW - 1;
            if (w < 0) w = 0;
            unsigned int word = ((const unsigned int*)bufs[b])[w];
            int m = (int)((word >> 8) & 0x7F);       // bf16: sign-stripped exponent bits
            if (m >= 0x35 && m <= 0x44) atomicAdd(&cnt[b], 1);
        }
    }
    int local = 0;
    for (int w = 1 + 2 * t; w < 2 * EE; w += 2 * 512)
        if (eidx[w] != 0u) local = 1;                // int64 in [0,192): odd words 0
    if (local) atomicOr(&nz, 1);
    __syncthreads();

    if (t < 5) g_bf[t] = (cnt[t] >= 64) ? 1 : 0;     // ambiguous => bf16 (never overreads)
    const int is64 = (nz == 0);
    for (int n = t; n < 2 * EE; n += 512) {
        int v = is64 ? (int)eidx[2 * n] : (int)eidx[n];
        if (v < 0) v = 0;
        if (v >= AA) v = AA - 1;
        g_eidx[n] = v;
    }
}

__device__ void featmap(int po, int qo, int* p, float* f) {
    int bi = (po == 0) ? 0 : (po < 4 ? 1 : 2);
    int bj = (qo == 0) ? 0 : (qo < 4 ? 1 : 2);
    if (bi > bj) { *p = -1; *f = 0.f; return; }
    *f = (bi == bj) ? 0.5f : 1.0f;
    int ri = po - (bi == 0 ? 0 : (bi == 1 ? 1 : 4));
    int ci = qo - (bj == 0 ? 0 : (bj == 1 ? 1 : 4));
    int jo = (bj == 0 ? 1 : (bj == 1 ? 3 : 5));
    int b;
    if (bi == 0)      b = (bj == 0) ? 0 : (bj == 1 ? 1 : 4);
    else if (bi == 1) b = (bj == 1) ? 9 : 18;
    else              b = 33;
    *p = b + ri * jo + ci;
}

// Fused rotate: grid = EE + AA blocks of 324 threads.
//   blocks [0, EE):   hop edges — rotate + transposed copy + Bloch phases
//                     (threads 0..3) + linked-list fill (thread 0)
//   blocks [EE, +AA): onsite — rotate only
// out = Rs @ H2 @ Rd^T with spin-interleaved doubling H2[2po+s,2qo+s]=Horb[po,qo].
__global__ void k_rotate(const void* feats, const void* ons,
                         const void* R, const void* kpts, const void* shift) {
    const int isOnsite = (blockIdx.x >= EE);
    const int e = isOnsite ? (blockIdx.x - EE) : blockIdx.x;
    const int t = threadIdx.x;   // 0..323
    __shared__ float Rs[SQ], Rd[SQ], Horb[81], M[SQ], O[SQ];

    const int bfF = g_bf[isOnsite ? 1 : 0];
    const int bfR = g_bf[2];
    const void* f = isOnsite ? ons : feats;

    int src, dst;
    if (isOnsite) { src = e; dst = e; }
    else          { src = g_eidx[e]; dst = g_eidx[EE + e]; }   // clamped

    Rs[t] = loadF(R, (long long)src * SQ + t, bfR);
    Rd[t] = loadF(R, (long long)dst * SQ + t, bfR);
    if (t < 81) {
        int po = t / 9, qo = t % 9, p; float fac;
        featmap(po, qo, &p, &fac);
        Horb[t] = (p >= 0) ? fac * loadF(f, (long long)e * PP + p, bfF) : 0.f;
    }
    if (!isOnsite) {
        if (t < KK) {   // Bloch phase exp(-2*pi*i k.S_e)
            const int bfK = g_bf[3], bfS = g_bf[4];
            float d = 0.f;
            for (int c = 0; c < 3; ++c)
                d += loadF(kpts, t * 3 + c, bfK) * loadF(shift, e * 3 + c, bfS);
            float sn, cs;
            sincosf(-6.283185307179586f * d, &sn, &cs);
            g_phc[e * KK + t] = cs;
            g_phs[e * KK + t] = sn;
        }
        if (t == 0) {   // pair binning via lock-free list push
            int pair = src * AA + dst;
            g_next[e] = atomicExch(&g_head[pair], e);
        }
    }
    __syncthreads();

    {   // Stage 1: M[i,q] = sum_po Rs[i, 2po+sq] * Horb[po, qo], q = 2qo+sq
        int i = t / SS, q = t % SS;
        int qo = q >> 1, sq = q & 1;
        float m = 0.f;
#pragma unroll
        for (int po = 0; po < 9; ++po)
            m += Rs[i * SS + 2 * po + sq] * Horb[po * 9 + qo];
        M[i * SS + q] = m;
    }
    __syncthreads();

    {   // Stage 2: O[i,j] = sum_q M[i,q] * Rd[j,q]
        int i = t / SS, j = t % SS;
        float o = 0.f;
#pragma unroll
        for (int q = 0; q < SS; ++q)
            o += M[i * SS + q] * Rd[j * SS + q];
        O[t] = o;
    }
    __syncthreads();

    if (isOnsite) {
        g_onRot[(long long)e * SQ + t] = O[t];
    } else {
        int i = t / SS, j = t % SS;
        g_hopRot[(long long)e * SQ + t] = O[t];
        g_hopT  [(long long)e * SQ + t] = O[j * SS + i];   // coalesced store
    }
}

// Store-once dense assembly, all KK k-planes fused per block. Edge sets come
// from per-pair linked lists (uniform broadcast walks, ~0.08 edges/pair avg).
// Streaming stores (__stcs): output is written once, never re-read.
__global__ void k_hk(float* out, int mode) {
    const int pair = blockIdx.x;
    const int pa = pair / AA, pb = pair % AA;
    const int pairT = pb * AA + pa;
    const int t = threadIdx.x;            // 0..323
    const int i = t / SS, j = t % SS;

    float re[KK], im[KK];
#pragma unroll
    for (int k = 0; k < KK; ++k) { re[k] = 0.f; im[k] = 0.f; }

    for (int e = g_head[pair]; e >= 0; e = g_next[e]) {    // direct: ph * hop[e][i,j]
        float v = g_hopRot[(long long)e * SQ + t];
#pragma unroll
        for (int k = 0; k < KK; ++k) {
            float c = g_phc[e * KK + k], s = g_phs[e * KK + k];
            re[k] += v * c;
            im[k] += v * s;
        }
    }
    for (int e = g_head[pairT]; e >= 0; e = g_next[e]) {   // reverse: conj(ph)*hop[e][j,i]
        float v = g_hopT[(long long)e * SQ + t];
#pragma unroll
        for (int k = 0; k < KK; ++k) {
            float c = g_phc[e * KK + k], s = g_phs[e * KK + k];
            re[k] += v * c;
            im[k] -= v * s;
        }
    }
    if (pa == pb) {                       // onsite + onsite^T (real, k-indep)
        float v = g_onRot[(long long)pa * SQ + i * SS + j]
                + g_onRot[(long long)pa * SQ + j * SS + i];
#pragma unroll
        for (int k = 0; k < KK; ++k) re[k] += v;
    }

    const long long row = (long long)pa * SS + i;
    const long long col = (long long)pb * SS + j;
    const long long base = row * NN + col;
    if (mode == 0) {
#pragma unroll
        for (int k = 0; k < KK; ++k) {
            long long cIdx = (long long)k * NN * NN + base;
            __stcs((float2*)(out + 2 * cIdx), make_float2(re[k], im[k]));
        }
    } else {
#pragma unroll
        for (int k = 0; k < KK; ++k)
            __stcs(out + (long long)k * NN * NN + base, re[k]);
    }
}

extern "C" void kernel_launch(void* const* d_in, const int* in_sizes, int n_in,
                              void* d_out, int out_size) {
    // Logical element counts: hop, onsite, R, kpoints, shift, edge_index
    const long long elemSz[6] = { (long long)EE * PP, (long long)AA * PP,
                                  (long long)AA * SQ, KK * 3, EE * 3, 2 * EE };
    const void* ptr[6] = { 0, 0, 0, 0, 0, 0 };

    int nin = n_in;
    if (nin < 0)  nin = 0;
    if (nin > 32) nin = 32;

    int matched = 1;
    for (int s = 0; s < 6 && matched; ++s) {
        int found = 0;
        for (int i = 0; i < nin && !found; ++i)
            if ((long long)in_sizes[i] == elemSz[s]) { ptr[s] = d_in[i]; found = 1; }
        matched = found;
    }

    float* out = (float*)d_out;
    const long long os = (long long)out_size;

    int mode;
    if (os == 2 * OUTC)       mode = 0;   // float32 view of complex (interleaved)
    else if (os == 8 * OUTC)  mode = 0;   // bytes of complex buffer
    else if (os == OUTC)      mode = 1;   // real-part-only world (safe half-fill)
    else                      mode = -1;

    if (!matched || mode < 0) {
        long long nz = os / 4;
        if (nz > 2 * OUTC) nz = 2 * OUTC;
        if (nz < 0) nz = 0;
        k_zero<<<4096, 512>>>(out, nz);
        return;
    }

    const void* hop   = ptr[0];
    const void* ons   = ptr[1];
    const void* R     = ptr[2];
    const void* kpts  = ptr[3];
    const void* shift = ptr[4];
    const unsigned int* eidxR = (const unsigned int*)ptr[5];

    k_detect<<<64, 512>>>(hop, ons, R, kpts, shift, eidxR);    // block0: sniff; rest: clr
    k_rotate<<<EE + AA, SQ>>>(hop, ons, R, kpts, shift);       // + phase + fill fused
    k_hk<<<NPAIR, SQ>>>(out, mode);   // every output element stored exactly once
}

// round 17
// speedup vs baseline: 3.6422x; 1.0056x over previous
#include <cuda_runtime.h>
#include <cuda_bf16.h>

// Problem constants (single species, e3tb 1s+1p+1d, K=4, A=192, E=3072)
#define AA 192
#define EE 3072
#define KK 4
#define PP 58
#define SS 18                          // spin_deg * norb
#define SQ (SS*SS)                     // 324
#define NN (AA*SS)                     // 3456
#define NPAIR (AA*AA)                  // 36864
#define OUTC ((long long)KK*NN*NN)     // complex64 elements = 47,775,744

// Scratch (__device__ globals)
__device__ float g_hopRot[EE * SQ];
__device__ float g_hopT  [EE * SQ];    // transposed copy for coalesced conj path
__device__ float g_onRot [AA * SQ];
__device__ int   g_head  [NPAIR];      // per-pair linked list head (-1 = empty)
__device__ int   g_next  [EE];         // chain links
__device__ float g_phc   [EE * KK];
__device__ float g_phs   [EE * KK];
__device__ int   g_bf    [5];          // per-float-buffer bf16 flag
__device__ int   g_is64;               // edge_index dtype flag

// ---------------------------------------------------------------------------
__device__ __forceinline__ float loadF(const void* p, long long i, int bf) {
    if (bf) return __bfloat162float(((const __nv_bfloat16*)p)[i]);
    return ((const float*)p)[i];
}

__global__ void k_zero(float* p, long long nFloats) {
    long long i = (long long)blockIdx.x * blockDim.x + threadIdx.x;
    long long st = (long long)gridDim.x * blockDim.x;
    while (i < nFloats) { p[i] = 0.0f; i += st; }
}

// Sampling-only detect. Blocks >= 1: clear list heads (grid-stride). Block 0:
// dtype sniff via 256 samples per buffer. eidx odd-word samples stay < 6144
// (present under int32 AND int64); 256 all-zero odd samples => int64 with
// error probability (1/192)^256 ~ 0.
__global__ void k_detect(const void* hop, const void* ons, const void* Rm,
                         const void* kp, const void* sh,
                         const unsigned int* eidx) {
    const int t = threadIdx.x;   // 512
    if (blockIdx.x != 0) {
        for (int i = (blockIdx.x - 1) * 512 + t; i < NPAIR; i += (gridDim.x - 1) * 512)
            g_head[i] = -1;
        return;
    }

    __shared__ int cnt[5];
    __shared__ int nz;
    if (t < 5) cnt[t] = 0;
    if (t == 0) nz = 0;
    __syncthreads();

    const void* bufs[5] = { hop, ons, Rm, kp, sh };
    const long long nels[5] = { (long long)EE * PP, (long long)AA * PP,
                                (long long)AA * SQ, KK * 3, EE * 3 };
    if (t < 256) {
        for (int b = 0; b < 5; ++b) {
            long long maxW = nels[b] / 2;            // words present under bf16 or f32
            long long w = ((long long)t * maxW) / 256;
            if (w >= maxW) w = maxW - 1;
            if (w < 0) w = 0;
            unsigned int word = ((const unsigned int*)bufs[b])[w];
            int m = (int)((word >> 8) & 0x7F);       // bf16: sign-stripped exponent bits
            if (m >= 0x35 && m <= 0x44) atomicAdd(&cnt[b], 1);
        }
        // eidx dtype: sample 256 odd words spread over [1, 6143]
        int w = 1 + 2 * ((t * 3071) / 256);
        if (eidx[w] != 0u) atomicOr(&nz, 1);         // int64 in [0,192): odd words 0
    }
    __syncthreads();

    if (t < 5) g_bf[t] = (cnt[t] >= 64) ? 1 : 0;     // ambiguous => bf16 (never overreads)
    if (t == 0) g_is64 = (nz == 0);
}

__device__ void featmap(int po, int qo, int* p, float* f) {
    int bi = (po == 0) ? 0 : (po < 4 ? 1 : 2);
    int bj = (qo == 0) ? 0 : (qo < 4 ? 1 : 2);
    if (bi > bj) { *p = -1; *f = 0.f; return; }
    *f = (bi == bj) ? 0.5f : 1.0f;
    int ri = po - (bi == 0 ? 0 : (bi == 1 ? 1 : 4));
    int ci = qo - (bj == 0 ? 0 : (bj == 1 ? 1 : 4));
    int jo = (bj == 0 ? 1 : (bj == 1 ? 3 : 5));
    int b;
    if (bi == 0)      b = (bj == 0) ? 0 : (bj == 1 ? 1 : 4);
    else if (bi == 1) b = (bj == 1) ? 9 : 18;
    else              b = 33;
    *p = b + ri * jo + ci;
}

// Fused rotate: grid = EE + AA blocks of 324 threads.
//   blocks [0, EE):   hop edges — rotate + transposed copy + Bloch phases
//                     (threads 0..3) + linked-list fill (thread 0)
//   blocks [EE, +AA): onsite — rotate only
// Edge indices read RAW (dtype-branched, clamped) — no normalization pass.
__global__ void k_rotate(const void* feats, const void* ons, const void* R,
                         const void* kpts, const void* shift,
                         const unsigned int* eidx) {
    const int isOnsite = (blockIdx.x >= EE);
    const int e = isOnsite ? (blockIdx.x - EE) : blockIdx.x;
    const int t = threadIdx.x;   // 0..323
    __shared__ float Rs[SQ], Rd[SQ], Horb[81], M[SQ], O[SQ];

    const int bfF = g_bf[isOnsite ? 1 : 0];
    const int bfR = g_bf[2];
    const void* f = isOnsite ? ons : feats;

    int src, dst;
    if (isOnsite) { src = e; dst = e; }
    else {
        const int is64 = g_is64;   // uniform broadcast
        src = is64 ? (int)eidx[2 * e]          : (int)eidx[e];
        dst = is64 ? (int)eidx[2 * (EE + e)]   : (int)eidx[EE + e];
        if (src < 0) src = 0;  if (src >= AA) src = AA - 1;
        if (dst < 0) dst = 0;  if (dst >= AA) dst = AA - 1;
    }

    Rs[t] = loadF(R, (long long)src * SQ + t, bfR);
    Rd[t] = loadF(R, (long long)dst * SQ + t, bfR);
    if (t < 81) {
        int po = t / 9, qo = t % 9, p; float fac;
        featmap(po, qo, &p, &fac);
        Horb[t] = (p >= 0) ? fac * loadF(f, (long long)e * PP + p, bfF) : 0.f;
    }
    if (!isOnsite) {
        if (t < KK) {   // Bloch phase exp(-2*pi*i k.S_e)
            const int bfK = g_bf[3], bfS = g_bf[4];
            float d = 0.f;
            for (int c = 0; c < 3; ++c)
                d += loadF(kpts, t * 3 + c, bfK) * loadF(shift, e * 3 + c, bfS);
            float sn, cs;
            sincosf(-6.283185307179586f * d, &sn, &cs);
            g_phc[e * KK + t] = cs;
            g_phs[e * KK + t] = sn;
        }
        if (t == 0) {   // pair binning via lock-free list push
            int pair = src * AA + dst;
            g_next[e] = atomicExch(&g_head[pair], e);
        }
    }
    __syncthreads();

    {   // Stage 1: M[i,q] = sum_po Rs[i, 2po+sq] * Horb[po, qo], q = 2qo+sq
        int i = t / SS, q = t % SS;
        int qo = q >> 1, sq = q & 1;
        float m = 0.f;
#pragma unroll
        for (int po = 0; po < 9; ++po)
            m += Rs[i * SS + 2 * po + sq] * Horb[po * 9 + qo];
        M[i * SS + q] = m;
    }
    __syncthreads();

    {   // Stage 2: O[i,j] = sum_q M[i,q] * Rd[j,q]
        int i = t / SS, j = t % SS;
        float o = 0.f;
#pragma unroll
        for (int q = 0; q < SS; ++q)
            o += M[i * SS + q] * Rd[j * SS + q];
        O[t] = o;
    }
    __syncthreads();

    if (isOnsite) {
        g_onRot[(long long)e * SQ + t] = O[t];
    } else {
        int i = t / SS, j = t % SS;
        g_hopRot[(long long)e * SQ + t] = O[t];
        g_hopT  [(long long)e * SQ + t] = O[j * SS + i];   // coalesced store
    }
}

// Store-once dense assembly, all KK k-planes fused per block. Edge sets come
// from per-pair linked lists (uniform broadcast walks, ~0.08 edges/pair avg).
// Streaming stores (__stcs): output is written once, never re-read.
__global__ void k_hk(float* out, int mode) {
    const int pair = blockIdx.x;
    const int pa = pair / AA, pb = pair % AA;
    const int pairT = pb * AA + pa;
    const int t = threadIdx.x;            // 0..323
    const int i = t / SS, j = t % SS;

    float re[KK], im[KK];
#pragma unroll
    for (int k = 0; k < KK; ++k) { re[k] = 0.f; im[k] = 0.f; }

    for (int e = g_head[pair]; e >= 0; e = g_next[e]) {    // direct: ph * hop[e][i,j]
        float v = g_hopRot[(long long)e * SQ + t];
#pragma unroll
        for (int k = 0; k < KK; ++k) {
            float c = g_phc[e * KK + k], s = g_phs[e * KK + k];
            re[k] += v * c;
            im[k] += v * s;
        }
    }
    for (int e = g_head[pairT]; e >= 0; e = g_next[e]) {   // reverse: conj(ph)*hop[e][j,i]
        float v = g_hopT[(long long)e * SQ + t];
#pragma unroll
        for (int k = 0; k < KK; ++k) {
            float c = g_phc[e * KK + k], s = g_phs[e * KK + k];
            re[k] += v * c;
            im[k] -= v * s;
        }
    }
    if (pa == pb) {                       // onsite + onsite^T (real, k-indep)
        float v = g_onRot[(long long)pa * SQ + i * SS + j]
                + g_onRot[(long long)pa * SQ + j * SS + i];
#pragma unroll
        for (int k = 0; k < KK; ++k) re[k] += v;
    }

    const long long row = (long long)pa * SS + i;
    const long long col = (long long)pb * SS + j;
    const long long base = row * NN + col;
    if (mode == 0) {
#pragma unroll
        for (int k = 0; k < KK; ++k) {
            long long cIdx = (long long)k * NN * NN + base;
            __stcs((float2*)(out + 2 * cIdx), make_float2(re[k], im[k]));
        }
    } else {
#pragma unroll
        for (int k = 0; k < KK; ++k)
            __stcs(out + (long long)k * NN * NN + base, re[k]);
    }
}

extern "C" void kernel_launch(void* const* d_in, const int* in_sizes, int n_in,
                              void* d_out, int out_size) {
    // Logical element counts: hop, onsite, R, kpoints, shift, edge_index
    const long long elemSz[6] = { (long long)EE * PP, (long long)AA * PP,
                                  (long long)AA * SQ, KK * 3, EE * 3, 2 * EE };
    const void* ptr[6] = { 0, 0, 0, 0, 0, 0 };

    int nin = n_in;
    if (nin < 0)  nin = 0;
    if (nin > 32) nin = 32;

    int matched = 1;
    for (int s = 0; s < 6 && matched; ++s) {
        int found = 0;
        for (int i = 0; i < nin && !found; ++i)
            if ((long long)in_sizes[i] == elemSz[s]) { ptr[s] = d_in[i]; found = 1; }
        matched = found;
    }

    float* out = (float*)d_out;
    const long long os = (long long)out_size;

    int mode;
    if (os == 2 * OUTC)       mode = 0;   // float32 view of complex (interleaved)
    else if (os == 8 * OUTC)  mode = 0;   // bytes of complex buffer
    else if (os == OUTC)      mode = 1;   // real-part-only world (safe half-fill)
    else                      mode = -1;

    if (!matched || mode < 0) {
        long long nz = os / 4;
        if (nz > 2 * OUTC) nz = 2 * OUTC;
        if (nz < 0) nz = 0;
        k_zero<<<4096, 512>>>(out, nz);
        return;
    }

    const void* hop   = ptr[0];
    const void* ons   = ptr[1];
    const void* R     = ptr[2];
    const void* kpts  = ptr[3];
    const void* shift = ptr[4];
    const unsigned int* eidxR = (const unsigned int*)ptr[5];

    k_detect<<<64, 512>>>(hop, ons, R, kpts, shift, eidxR);        // sample-only sniff + clr
    k_rotate<<<EE + AA, SQ>>>(hop, ons, R, kpts, shift, eidxR);    // + phase + fill fused
    k_hk<<<NPAIR, SQ>>>(out, mode);   // every output element stored exactly once
}